// round 9
// baseline (speedup 1.0000x reference)
#include <cuda_runtime.h>
#include <cstdint>

// Energy distance, B=16, N=M=256, D=128, fp32. SINGLE-LAUNCH version.
// Per (batch, dim): normalized (all-ascending) bitonic sort of the 512 merged
// labeled values, 8 elems/thread, 64 threads/column (2 warps), hybrid
// register/shfl/smem exchanges. Then E*N^2 = sum_k (z_{k+1}-z_k) * d_k^2 with
// d = prefix of +/-1 labels (label in fp32 mantissa LSB).
// Cross-CTA reduction via __device__ scratch + per-batch arrival counter
// (last CTA of each batch writes out[b] and resets the counter for replay).

#define EB 16
#define EN 256
#define ED 128
#define HALF 272    // float offset of second register-half (bank-shifted)
#define CSZ 528     // floats per column buffer
#define GX 32       // grid.x = ED/4
#define FULL_MASK 0xFFFFFFFFu

__device__ float g_part[EB][GX];
__device__ int   g_cnt[EB];        // zero-initialized; reset by last CTA each run

__device__ __forceinline__ void colbar(int col) {
    asm volatile("bar.sync %0, 64;" :: "r"(col + 1) : "memory");
}

// In-register ascending compare-exchange.
#define CEP(a, bq) { const float lo_ = fminf((a), (bq)); const float hi_ = fmaxf((a), (bq)); (a) = lo_; (bq) = hi_; }
#define INREG_J4 { CEP(v[0],v[4]) CEP(v[1],v[5]) CEP(v[2],v[6]) CEP(v[3],v[7]) }
#define INREG_J2 { CEP(v[0],v[2]) CEP(v[1],v[3]) CEP(v[4],v[6]) CEP(v[5],v[7]) }
#define INREG_J1 { CEP(v[0],v[1]) CEP(v[2],v[3]) CEP(v[4],v[5]) CEP(v[6],v[7]) }

#define STORE_PH { \
    *(float4*)(bufs[ph] + (tid_c << 2))        = make_float4(v[0], v[1], v[2], v[3]); \
    *(float4*)(bufs[ph] + HALF + (tid_c << 2)) = make_float4(v[4], v[5], v[6], v[7]); }

#define LOAD_FWD(pp, u) { \
    const float4 ua_ = *(const float4*)(bufs[ph] + ((pp) << 2)); \
    const float4 ub_ = *(const float4*)(bufs[ph] + HALF + ((pp) << 2)); \
    u[0]=ua_.x; u[1]=ua_.y; u[2]=ua_.z; u[3]=ua_.w; \
    u[4]=ub_.x; u[5]=ub_.y; u[6]=ub_.z; u[7]=ub_.w; }

#define LOAD_REV(pp, u) { \
    const float4 ua_ = *(const float4*)(bufs[ph] + ((pp) << 2)); \
    const float4 ub_ = *(const float4*)(bufs[ph] + HALF + ((pp) << 2)); \
    u[0]=ub_.w; u[1]=ub_.z; u[2]=ub_.y; u[3]=ub_.x; \
    u[4]=ua_.w; u[5]=ua_.z; u[6]=ua_.y; u[7]=ua_.x; }

#define CEALL(u, P) { \
    _Pragma("unroll") for (int r_ = 0; r_ < 8; r_++) \
        v[r_] = (P) ? fminf(v[r_], u[r_]) : fmaxf(v[r_], u[r_]); }

// Triangle stage via warp-private smem (partner lane tid_c^mask, regs reversed).
#define TRI_W(mask, P) { float u[8]; STORE_PH; __syncwarp(); LOAD_REV(tid_c ^ (mask), u); CEALL(u, P); ph ^= 1; }
// Substage via smem.
#define SUB_SMEM(m, P) { float u[8]; STORE_PH; __syncwarp(); LOAD_FWD(tid_c ^ (m), u); CEALL(u, P); ph ^= 1; }
// Substage via shfl.
#define SUB_SHFL(m, P) { \
    _Pragma("unroll") for (int r_ = 0; r_ < 8; r_++) { \
        const float u_ = __shfl_xor_sync(FULL_MASK, v[r_], (m)); \
        v[r_] = (P) ? fminf(v[r_], u_) : fmaxf(v[r_], u_); } }

__global__ __launch_bounds__(256) void ed_kernel(
    const float* __restrict__ x1,
    const float* __restrict__ x2,
    float* __restrict__ out)
{
    __shared__ __align__(16) float sbuf[2][4][CSZ];  // ping-pong exchange buffers
    __shared__ float nb[4][65];
    __shared__ float ws[4][2];
    __shared__ float cr[4][2];

    const int b  = blockIdx.y;
    const int d0 = blockIdx.x << 2;        // 4 dims per CTA
    const int t  = threadIdx.x;
    const int lane  = t & 31;
    const int col   = t >> 6;              // 0..3
    const int wc    = (t >> 5) & 1;        // warp within column
    const int tid_c = t & 63;              // thread within column

    // ---- Stage: coalesced float4 loads, labels in mantissa LSB (x1->1, x2->0),
    //      scattered into split-half register layout:
    //      addr(i) = (i&4 ? HALF : 0) + (i>>3)*4 + (i&3); x1 at i=s, x2 at i=256+s.
    {
        const size_t off = ((size_t)(b * EN + t)) * ED + d0;
        const float4 a4 = *(const float4*)(x1 + off);
        const float4 b4 = *(const float4*)(x2 + off);
        const uint32_t au[4] = {__float_as_uint(a4.x) |  1u, __float_as_uint(a4.y) |  1u,
                                __float_as_uint(a4.z) |  1u, __float_as_uint(a4.w) |  1u};
        const uint32_t bu[4] = {__float_as_uint(b4.x) & ~1u, __float_as_uint(b4.y) & ~1u,
                                __float_as_uint(b4.z) & ~1u, __float_as_uint(b4.w) & ~1u};
        const int ad = ((t & 4) ? HALF : 0) + ((t >> 3) << 2) + (t & 3);
        #pragma unroll
        for (int c = 0; c < 4; c++) {
            sbuf[0][c][ad]       = __uint_as_float(au[c]);   // i = t
            sbuf[0][c][ad + 128] = __uint_as_float(bu[c]);   // i = 256 + t
        }
    }
    __syncthreads();

    float* bufs[2] = { sbuf[0][col], sbuf[1][col] };
    int ph = 0;

    float v[8];
    {
        const float4 a  = *(const float4*)(bufs[0] + (tid_c << 2));
        const float4 c4 = *(const float4*)(bufs[0] + HALF + (tid_c << 2));
        v[0]=a.x;  v[1]=a.y;  v[2]=a.z;  v[3]=a.w;
        v[4]=c4.x; v[5]=c4.y; v[6]=c4.z; v[7]=c4.w;
    }

    // keep-min predicates (all comparators ascending in normalized bitonic)
    const bool P1  = (lane & 1)  == 0;
    const bool P2  = (lane & 2)  == 0;
    const bool P4  = (lane & 4)  == 0;
    const bool P8  = (lane & 8)  == 0;
    const bool P16 = (lane & 16) == 0;
    const bool PW  = (wc == 0);

    // ---- Normalized bitonic sort of 512 (i = 8*tid_c + r) ----
    // K=2
    INREG_J1
    // K=4: triangle r^3, then j=1
    CEP(v[0],v[3]) CEP(v[1],v[2]) CEP(v[4],v[7]) CEP(v[5],v[6])
    INREG_J1
    // K=8: triangle r^7, then j=2,1
    CEP(v[0],v[7]) CEP(v[1],v[6]) CEP(v[2],v[5]) CEP(v[3],v[4])
    INREG_J2 INREG_J1
    // K=16
    TRI_W(1, P1)
    INREG_J4 INREG_J2 INREG_J1
    // K=32
    TRI_W(3, P2)  SUB_SHFL(1, P1)
    INREG_J4 INREG_J2 INREG_J1
    // K=64
    TRI_W(7, P4)  SUB_SHFL(2, P2) SUB_SHFL(1, P1)
    INREG_J4 INREG_J2 INREG_J1
    // K=128
    TRI_W(15, P8) SUB_SMEM(4, P4) SUB_SHFL(2, P2) SUB_SHFL(1, P1)
    INREG_J4 INREG_J2 INREG_J1
    // K=256
    TRI_W(31, P16) SUB_SMEM(8, P8) SUB_SMEM(4, P4) SUB_SHFL(2, P2) SUB_SHFL(1, P1)
    INREG_J4 INREG_J2 INREG_J1
    // K=512: cross-warp triangle (tid_c^63) -> named barrier pair
    {
        float u[8];
        STORE_PH;
        colbar(col);
        LOAD_REV(tid_c ^ 63, u);
        CEALL(u, PW);
        colbar(col);
        ph ^= 1;
    }
    SUB_SMEM(16, P16) SUB_SMEM(8, P8) SUB_SMEM(4, P4) SUB_SHFL(2, P2) SUB_SHFL(1, P1)
    INREG_J4 INREG_J2 INREG_J1

    // ---- Label prefix d (float, exact): +1 for x1 (LSB=1), -1 for x2 ----
    float c[8];
    c[0] = (__float_as_uint(v[0]) & 1u) ? 1.0f : -1.0f;
    #pragma unroll
    for (int r = 1; r < 8; r++)
        c[r] = c[r-1] + ((__float_as_uint(v[r]) & 1u) ? 1.0f : -1.0f);

    float incl = c[7];
    #pragma unroll
    for (int o = 1; o < 32; o <<= 1) {
        const float f = __shfl_up_sync(FULL_MASK, incl, o);
        if (lane >= o) incl += f;
    }

    nb[col][tid_c] = v[0];
    if (lane == 31) ws[col][wc] = incl;
    if (tid_c == 63) nb[col][64] = v[7];   // zero final gap (d there = 0 anyway)
    colbar(col);

    const float dbase = incl - c[7] + (wc ? ws[col][0] : 0.0f);

    float vn7 = __shfl_down_sync(FULL_MASK, v[0], 1);
    if (lane == 31) vn7 = nb[col][tid_c + 1];

    float acc = 0.0f;
    #pragma unroll
    for (int r = 0; r < 7; r++) {
        const float dr = dbase + c[r];
        acc += (v[r+1] - v[r]) * dr * dr;
    }
    {
        const float dr = dbase + c[7];
        acc += (vn7 - v[7]) * dr * dr;
    }

    // ---- Reduce: warp -> CTA -> device scratch -> last CTA writes out[b] ----
    #pragma unroll
    for (int o = 16; o; o >>= 1)
        acc += __shfl_xor_sync(FULL_MASK, acc, o);
    if (lane == 0) cr[col][wc] = acc;
    __syncthreads();

    if (t == 0) {
        float s = 0.0f;
        #pragma unroll
        for (int cc = 0; cc < 4; cc++) s += cr[cc][0] + cr[cc][1];
        g_part[b][blockIdx.x] = s;
        __threadfence();
        const int old = atomicAdd(&g_cnt[b], 1);
        if (old == GX - 1) {
            __threadfence();
            float tot = 0.0f;
            #pragma unroll 8
            for (int i = 0; i < GX; i++) tot += g_part[b][i];
            out[b] = tot * (1.0f / (float)(EN * EN));
            g_cnt[b] = 0;   // reset for next graph replay
        }
    }
}

extern "C" void kernel_launch(void* const* d_in, const int* in_sizes, int n_in,
                              void* d_out, int out_size)
{
    const float* x1 = (const float*)d_in[0];
    const float* x2 = (const float*)d_in[1];
    float* out = (float*)d_out;

    dim3 grid(GX, EB);   // (32, 16): 4 dims per CTA, 2 warps per dim
    ed_kernel<<<grid, 256>>>(x1, x2, out);
}

// round 10
// speedup vs baseline: 1.0247x; 1.0247x over previous
#include <cuda_runtime.h>
#include <cstdint>

// Energy distance, B=16, N=M=256, D=128, fp32. Single launch.
// Per (batch, dim): 512-value merged labeled sort done ENTIRELY inside one
// warp (16 elems/thread), normalized all-ascending bitonic with hybrid
// register / shfl / warp-private-smem exchanges. Zero block barriers in the
// sort. E*N^2 = sum_k (z_{k+1}-z_k)*d_k^2, d = prefix of +/-1 labels
// (label in fp32 mantissa LSB). Cross-CTA fan-in: one float atomicAdd per
// CTA into device scratch + arrival counter; last CTA of each batch writes
// out[b] and resets scratch for graph replay.

#define EB 16
#define EN 256
#define ED 128
#define GX 16          // grid.x = ED/8 (8 dims per CTA, 1 warp per dim)
#define CSTRIDE 648    // floats per column buffer (pad: phys max 635)
#define FULL_MASK 0xFFFFFFFFu

__device__ float g_accum[EB];   // zero-init; reset by last CTA each run
__device__ int   g_cnt[EB];

// In-register ascending compare-exchange.
#define CEP(a,b) { const float lo_=fminf((a),(b)), hi_=fmaxf((a),(b)); (a)=lo_; (b)=hi_; }

#define IR_J1 { CEP(v[0],v[1]) CEP(v[2],v[3]) CEP(v[4],v[5]) CEP(v[6],v[7]) \
                CEP(v[8],v[9]) CEP(v[10],v[11]) CEP(v[12],v[13]) CEP(v[14],v[15]) }
#define IR_J2 { CEP(v[0],v[2]) CEP(v[1],v[3]) CEP(v[4],v[6]) CEP(v[5],v[7]) \
                CEP(v[8],v[10]) CEP(v[9],v[11]) CEP(v[12],v[14]) CEP(v[13],v[15]) }
#define IR_J4 { CEP(v[0],v[4]) CEP(v[1],v[5]) CEP(v[2],v[6]) CEP(v[3],v[7]) \
                CEP(v[8],v[12]) CEP(v[9],v[13]) CEP(v[10],v[14]) CEP(v[11],v[15]) }
#define IR_J8 { CEP(v[0],v[8]) CEP(v[1],v[9]) CEP(v[2],v[10]) CEP(v[3],v[11]) \
                CEP(v[4],v[12]) CEP(v[5],v[13]) CEP(v[6],v[14]) CEP(v[7],v[15]) }
#define IR_TRI4  { CEP(v[0],v[3]) CEP(v[1],v[2]) CEP(v[4],v[7]) CEP(v[5],v[6]) \
                   CEP(v[8],v[11]) CEP(v[9],v[10]) CEP(v[12],v[15]) CEP(v[13],v[14]) }
#define IR_TRI8  { CEP(v[0],v[7]) CEP(v[1],v[6]) CEP(v[2],v[5]) CEP(v[3],v[4]) \
                   CEP(v[8],v[15]) CEP(v[9],v[14]) CEP(v[10],v[13]) CEP(v[11],v[12]) }
#define IR_TRI16 { CEP(v[0],v[15]) CEP(v[1],v[14]) CEP(v[2],v[13]) CEP(v[3],v[12]) \
                   CEP(v[4],v[11]) CEP(v[5],v[10]) CEP(v[6],v[9]) CEP(v[7],v[8]) }
#define IR_TAIL { IR_J8 IR_J4 IR_J2 IR_J1 }

// Cross-lane substage via shfl (mask m over lanes), keep-min predicate P.
#define SH(m, P) { _Pragma("unroll") for (int r_=0;r_<16;r_++){ \
    const float u_=__shfl_xor_sync(FULL_MASK, v[r_], (m)); \
    v[r_]=(P)?fminf(v[r_],u_):fmaxf(v[r_],u_);} }

#define SM_STORE { \
    *(float4*)(buf+base)    = make_float4(v[0],v[1],v[2],v[3]); \
    *(float4*)(buf+base+4)  = make_float4(v[4],v[5],v[6],v[7]); \
    *(float4*)(buf+base+8)  = make_float4(v[8],v[9],v[10],v[11]); \
    *(float4*)(buf+base+12) = make_float4(v[12],v[13],v[14],v[15]); }

// Triangle via warp-private smem: partner lane^m, registers reversed.
#define SM_TRI(m, P) { __syncwarp(); SM_STORE; __syncwarp(); \
    const int pb_ = 20*(lane^(m)); \
    const float4 q0=*(const float4*)(buf+pb_),   q1=*(const float4*)(buf+pb_+4); \
    const float4 q2=*(const float4*)(buf+pb_+8), q3=*(const float4*)(buf+pb_+12); \
    const float u_[16]={q3.w,q3.z,q3.y,q3.x, q2.w,q2.z,q2.y,q2.x, \
                        q1.w,q1.z,q1.y,q1.x, q0.w,q0.z,q0.y,q0.x}; \
    _Pragma("unroll") for(int r_=0;r_<16;r_++) \
        v[r_]=(P)?fminf(v[r_],u_[r_]):fmaxf(v[r_],u_[r_]); }

// Substage via warp-private smem: partner lane^m, registers forward.
#define SM_FWD(m, P) { __syncwarp(); SM_STORE; __syncwarp(); \
    const int pb_ = 20*(lane^(m)); \
    const float4 q0=*(const float4*)(buf+pb_),   q1=*(const float4*)(buf+pb_+4); \
    const float4 q2=*(const float4*)(buf+pb_+8), q3=*(const float4*)(buf+pb_+12); \
    const float u_[16]={q0.x,q0.y,q0.z,q0.w, q1.x,q1.y,q1.z,q1.w, \
                        q2.x,q2.y,q2.z,q2.w, q3.x,q3.y,q3.z,q3.w}; \
    _Pragma("unroll") for(int r_=0;r_<16;r_++) \
        v[r_]=(P)?fminf(v[r_],u_[r_]):fmaxf(v[r_],u_[r_]); }

__global__ __launch_bounds__(256) void ed_kernel(
    const float* __restrict__ x1,
    const float* __restrict__ x2,
    float* __restrict__ out)
{
    __shared__ __align__(16) float stg[8 * CSTRIDE];
    __shared__ float wred[8];

    const int b  = blockIdx.y;
    const int d0 = blockIdx.x << 3;        // 8 dims per CTA
    const int t  = threadIdx.x;
    const int lane = t & 31;
    const int w    = t >> 5;               // warp == column (dim)

    // ---- Stage: thread t loads both inputs' sample t, dims d0..d0+7, labels
    //      into mantissa LSB (x1->1, x2->0). Layout per column: element
    //      i = 16*L + r at float offset 20*L + r (pad 4 per 16 -> LDS.128
    //      conflict-free). x1 at i=s (addr pt), x2 at i=256+s (addr pt+320).
    {
        const size_t off = ((size_t)(b * EN + t)) * ED + d0;
        const float4 a0 = *(const float4*)(x1 + off);
        const float4 a1 = *(const float4*)(x1 + off + 4);
        const float4 b0 = *(const float4*)(x2 + off);
        const float4 b1 = *(const float4*)(x2 + off + 4);
        const uint32_t av[8] = {
            __float_as_uint(a0.x)|1u, __float_as_uint(a0.y)|1u,
            __float_as_uint(a0.z)|1u, __float_as_uint(a0.w)|1u,
            __float_as_uint(a1.x)|1u, __float_as_uint(a1.y)|1u,
            __float_as_uint(a1.z)|1u, __float_as_uint(a1.w)|1u };
        const uint32_t bv[8] = {
            __float_as_uint(b0.x)&~1u, __float_as_uint(b0.y)&~1u,
            __float_as_uint(b0.z)&~1u, __float_as_uint(b0.w)&~1u,
            __float_as_uint(b1.x)&~1u, __float_as_uint(b1.y)&~1u,
            __float_as_uint(b1.z)&~1u, __float_as_uint(b1.w)&~1u };
        const int pt = t + ((t >> 4) << 2);          // phys(t)
        #pragma unroll
        for (int c = 0; c < 8; c++) {
            stg[c * CSTRIDE + pt]       = __uint_as_float(av[c]);
            stg[c * CSTRIDE + pt + 320] = __uint_as_float(bv[c]);
        }
    }
    __syncthreads();

    float* buf = stg + w * CSTRIDE;
    const int base = 20 * lane;

    float v[16];
    {
        const float4 q0=*(const float4*)(buf+base),   q1=*(const float4*)(buf+base+4);
        const float4 q2=*(const float4*)(buf+base+8), q3=*(const float4*)(buf+base+12);
        v[0]=q0.x; v[1]=q0.y; v[2]=q0.z; v[3]=q0.w;
        v[4]=q1.x; v[5]=q1.y; v[6]=q1.z; v[7]=q1.w;
        v[8]=q2.x; v[9]=q2.y; v[10]=q2.z; v[11]=q2.w;
        v[12]=q3.x; v[13]=q3.y; v[14]=q3.z; v[15]=q3.w;
    }

    const bool P1  = (lane & 1)  == 0;
    const bool P2  = (lane & 2)  == 0;
    const bool P4  = (lane & 4)  == 0;
    const bool P8  = (lane & 8)  == 0;
    const bool P16 = (lane & 16) == 0;

    // ---- Normalized bitonic sort of 512, all inside this warp ----
    IR_J1                                        // K=2
    IR_TRI4  IR_J1                               // K=4
    IR_TRI8  IR_J2 IR_J1                         // K=8
    IR_TRI16 IR_J4 IR_J2 IR_J1                   // K=16
    SM_TRI(1,  P1)                       IR_TAIL // K=32
    SM_TRI(3,  P2)             SH(1,P1)  IR_TAIL // K=64
    SM_TRI(7,  P4)   SH(2,P2)  SH(1,P1)  IR_TAIL // K=128
    SM_TRI(15, P8)  SM_FWD(4,P4) SH(2,P2) SH(1,P1) IR_TAIL          // K=256
    SM_TRI(31, P16) SM_FWD(8,P8) SM_FWD(4,P4) SH(2,P2) SH(1,P1) IR_TAIL // K=512

    // ---- Label prefix d (exact small ints in fp32) ----
    float c[16];
    c[0] = (__float_as_uint(v[0]) & 1u) ? 1.0f : -1.0f;
    #pragma unroll
    for (int r = 1; r < 16; r++)
        c[r] = c[r-1] + ((__float_as_uint(v[r]) & 1u) ? 1.0f : -1.0f);

    float incl = c[15];
    #pragma unroll
    for (int o = 1; o < 32; o <<= 1) {
        const float f = __shfl_up_sync(FULL_MASK, incl, o);
        if (lane >= o) incl += f;
    }
    const float dbase = incl - c[15];

    // Neighbor for the r=15 gap; lane 31's term has d=0 (labels sum to 0),
    // so its (self) shfl value is harmless.
    const float vn = __shfl_down_sync(FULL_MASK, v[0], 1);

    float acc = 0.0f;
    #pragma unroll
    for (int r = 0; r < 15; r++) {
        const float dr = dbase + c[r];
        acc += (v[r+1] - v[r]) * dr * dr;
    }
    {
        const float dr = dbase + c[15];
        acc += (vn - v[15]) * dr * dr;
    }

    // ---- Warp reduce -> CTA reduce -> device scratch fan-in ----
    #pragma unroll
    for (int o = 16; o; o >>= 1)
        acc += __shfl_xor_sync(FULL_MASK, acc, o);
    if (lane == 0) wred[w] = acc;
    __syncthreads();

    if (t == 0) {
        float s = 0.0f;
        #pragma unroll
        for (int i = 0; i < 8; i++) s += wred[i];
        atomicAdd(&g_accum[b], s * (1.0f / (float)(EN * EN)));
        __threadfence();
        const int old = atomicAdd(&g_cnt[b], 1);
        if (old == GX - 1) {
            const float tot = atomicAdd(&g_accum[b], 0.0f);  // atomic read
            out[b] = tot;
            __threadfence();
            g_accum[b] = 0.0f;   // reset for next graph replay
            g_cnt[b]   = 0;
        }
    }
}

extern "C" void kernel_launch(void* const* d_in, const int* in_sizes, int n_in,
                              void* d_out, int out_size)
{
    const float* x1 = (const float*)d_in[0];
    const float* x2 = (const float*)d_in[1];
    float* out = (float*)d_out;

    dim3 grid(GX, EB);   // (16, 16): 8 dims per CTA, 1 warp per dim
    ed_kernel<<<grid, 256>>>(x1, x2, out);
}

// round 11
// speedup vs baseline: 1.1315x; 1.1042x over previous
#include <cuda_runtime.h>
#include <cstdint>

// Energy distance, B=16, N=M=256, D=128, fp32. Single launch.
// Per (batch, dim): 512-value merged labeled sort entirely inside one warp
// (16 elems/thread), normalized all-ascending bitonic where ALL cross-thread
// stages are shfl (lane masks <= 31) -- zero smem, zero barriers in the sort,
// and triangle reversals are compile-time register permutations (no MOVs).
// E*N^2 = sum_k (z_{k+1}-z_k)*d_k^2, d = prefix of +/-1 labels (label in
// fp32 mantissa LSB). Cross-CTA fan-in via device scratch + arrival counter.

#define EB 16
#define EN 256
#define ED 128
#define GX 16          // grid.x = ED/8 (8 dims per CTA, 1 warp per dim)
#define CSTRIDE 648    // floats per staging column (phys max 635)
#define FULL_MASK 0xFFFFFFFFu

__device__ float g_accum[EB];   // zero-init; reset by last CTA each run
__device__ int   g_cnt[EB];

// In-register ascending compare-exchange.
#define CEP(a,b) { const float lo_=fminf((a),(b)), hi_=fmaxf((a),(b)); (a)=lo_; (b)=hi_; }

#define IR_J1 { CEP(v[0],v[1]) CEP(v[2],v[3]) CEP(v[4],v[5]) CEP(v[6],v[7]) \
                CEP(v[8],v[9]) CEP(v[10],v[11]) CEP(v[12],v[13]) CEP(v[14],v[15]) }
#define IR_J2 { CEP(v[0],v[2]) CEP(v[1],v[3]) CEP(v[4],v[6]) CEP(v[5],v[7]) \
                CEP(v[8],v[10]) CEP(v[9],v[11]) CEP(v[12],v[14]) CEP(v[13],v[15]) }
#define IR_J4 { CEP(v[0],v[4]) CEP(v[1],v[5]) CEP(v[2],v[6]) CEP(v[3],v[7]) \
                CEP(v[8],v[12]) CEP(v[9],v[13]) CEP(v[10],v[14]) CEP(v[11],v[15]) }
#define IR_J8 { CEP(v[0],v[8]) CEP(v[1],v[9]) CEP(v[2],v[10]) CEP(v[3],v[11]) \
                CEP(v[4],v[12]) CEP(v[5],v[13]) CEP(v[6],v[14]) CEP(v[7],v[15]) }
#define IR_TRI4  { CEP(v[0],v[3]) CEP(v[1],v[2]) CEP(v[4],v[7]) CEP(v[5],v[6]) \
                   CEP(v[8],v[11]) CEP(v[9],v[10]) CEP(v[12],v[15]) CEP(v[13],v[14]) }
#define IR_TRI8  { CEP(v[0],v[7]) CEP(v[1],v[6]) CEP(v[2],v[5]) CEP(v[3],v[4]) \
                   CEP(v[8],v[15]) CEP(v[9],v[14]) CEP(v[10],v[13]) CEP(v[11],v[12]) }
#define IR_TRI16 { CEP(v[0],v[15]) CEP(v[1],v[14]) CEP(v[2],v[13]) CEP(v[3],v[12]) \
                   CEP(v[4],v[11]) CEP(v[5],v[10]) CEP(v[6],v[9]) CEP(v[7],v[8]) }
#define IR_TAIL { IR_J8 IR_J4 IR_J2 IR_J1 }

// Cross-lane substage via shfl: partner lane^m, same register index.
#define SHS(m, P) { float u_[16]; \
    _Pragma("unroll") for (int r_=0;r_<16;r_++) \
        u_[r_] = __shfl_xor_sync(FULL_MASK, v[r_], (m)); \
    _Pragma("unroll") for (int r_=0;r_<16;r_++) \
        v[r_] = (P) ? fminf(v[r_],u_[r_]) : fmaxf(v[r_],u_[r_]); }

// Cross-lane triangle via shfl: partner lane^m, register index reversed.
// Reversal is a compile-time index permutation -- no data movement.
#define SHT(m, P) { float u_[16]; \
    _Pragma("unroll") for (int r_=0;r_<16;r_++) \
        u_[r_] = __shfl_xor_sync(FULL_MASK, v[15-r_], (m)); \
    _Pragma("unroll") for (int r_=0;r_<16;r_++) \
        v[r_] = (P) ? fminf(v[r_],u_[r_]) : fmaxf(v[r_],u_[r_]); }

__global__ __launch_bounds__(256) void ed_kernel(
    const float* __restrict__ x1,
    const float* __restrict__ x2,
    float* __restrict__ out)
{
    __shared__ __align__(16) float stg[8 * CSTRIDE];
    __shared__ float wred[8];

    const int b  = blockIdx.y;
    const int d0 = blockIdx.x << 3;        // 8 dims per CTA
    const int t  = threadIdx.x;
    const int lane = t & 31;
    const int w    = t >> 5;               // warp == column (dim)

    // ---- Stage: thread t loads both inputs' sample t, dims d0..d0+7, labels
    //      into mantissa LSB (x1->1, x2->0). Element i = 16*L + r lives at
    //      float offset 20*L + r (pad 4 per 16 -> LDS.128 conflict-free).
    {
        const size_t off = ((size_t)(b * EN + t)) * ED + d0;
        const float4 a0 = *(const float4*)(x1 + off);
        const float4 a1 = *(const float4*)(x1 + off + 4);
        const float4 b0 = *(const float4*)(x2 + off);
        const float4 b1 = *(const float4*)(x2 + off + 4);
        const uint32_t av[8] = {
            __float_as_uint(a0.x)|1u, __float_as_uint(a0.y)|1u,
            __float_as_uint(a0.z)|1u, __float_as_uint(a0.w)|1u,
            __float_as_uint(a1.x)|1u, __float_as_uint(a1.y)|1u,
            __float_as_uint(a1.z)|1u, __float_as_uint(a1.w)|1u };
        const uint32_t bv[8] = {
            __float_as_uint(b0.x)&~1u, __float_as_uint(b0.y)&~1u,
            __float_as_uint(b0.z)&~1u, __float_as_uint(b0.w)&~1u,
            __float_as_uint(b1.x)&~1u, __float_as_uint(b1.y)&~1u,
            __float_as_uint(b1.z)&~1u, __float_as_uint(b1.w)&~1u };
        const int pt = t + ((t >> 4) << 2);          // phys(t)
        #pragma unroll
        for (int c = 0; c < 8; c++) {
            stg[c * CSTRIDE + pt]       = __uint_as_float(av[c]);
            stg[c * CSTRIDE + pt + 320] = __uint_as_float(bv[c]);
        }
    }
    __syncthreads();

    const float* buf = stg + w * CSTRIDE;
    const int base = 20 * lane;

    float v[16];
    {
        const float4 q0=*(const float4*)(buf+base),   q1=*(const float4*)(buf+base+4);
        const float4 q2=*(const float4*)(buf+base+8), q3=*(const float4*)(buf+base+12);
        v[0]=q0.x; v[1]=q0.y; v[2]=q0.z; v[3]=q0.w;
        v[4]=q1.x; v[5]=q1.y; v[6]=q1.z; v[7]=q1.w;
        v[8]=q2.x; v[9]=q2.y; v[10]=q2.z; v[11]=q2.w;
        v[12]=q3.x; v[13]=q3.y; v[14]=q3.z; v[15]=q3.w;
    }

    // keep-min predicates: (i & K/2)==0 maps to one lane bit per level
    const bool P1  = (lane & 1)  == 0;
    const bool P2  = (lane & 2)  == 0;
    const bool P4  = (lane & 4)  == 0;
    const bool P8  = (lane & 8)  == 0;
    const bool P16 = (lane & 16) == 0;

    // ---- Normalized bitonic sort of 512, all in-warp, all-shfl cross-lane ----
    IR_J1                                        // K=2
    IR_TRI4  IR_J1                               // K=4
    IR_TRI8  IR_J2 IR_J1                         // K=8
    IR_TRI16 IR_J4 IR_J2 IR_J1                   // K=16
    SHT(1,  P1)                                       IR_TAIL  // K=32
    SHT(3,  P2)                            SHS(1, P1) IR_TAIL  // K=64
    SHT(7,  P4)                 SHS(2, P2) SHS(1, P1) IR_TAIL  // K=128
    SHT(15, P8)      SHS(4, P4) SHS(2, P2) SHS(1, P1) IR_TAIL  // K=256
    SHT(31, P16) SHS(8, P8) SHS(4, P4) SHS(2, P2) SHS(1, P1) IR_TAIL  // K=512

    // ---- Label prefix d (exact small ints in fp32) ----
    float c[16];
    c[0] = (__float_as_uint(v[0]) & 1u) ? 1.0f : -1.0f;
    #pragma unroll
    for (int r = 1; r < 16; r++)
        c[r] = c[r-1] + ((__float_as_uint(v[r]) & 1u) ? 1.0f : -1.0f);

    float incl = c[15];
    #pragma unroll
    for (int o = 1; o < 32; o <<= 1) {
        const float f = __shfl_up_sync(FULL_MASK, incl, o);
        if (lane >= o) incl += f;
    }
    const float dbase = incl - c[15];

    // Neighbor for the r=15 gap; lane 31's term has d=0 (labels sum to 0),
    // so its (self) shfl value is harmless.
    const float vn = __shfl_down_sync(FULL_MASK, v[0], 1);

    float acc = 0.0f;
    #pragma unroll
    for (int r = 0; r < 15; r++) {
        const float dr = dbase + c[r];
        acc += (v[r+1] - v[r]) * dr * dr;
    }
    {
        const float dr = dbase + c[15];
        acc += (vn - v[15]) * dr * dr;
    }

    // ---- Warp reduce -> CTA reduce -> device scratch fan-in ----
    #pragma unroll
    for (int o = 16; o; o >>= 1)
        acc += __shfl_xor_sync(FULL_MASK, acc, o);
    if (lane == 0) wred[w] = acc;
    __syncthreads();

    if (t == 0) {
        float s = 0.0f;
        #pragma unroll
        for (int i = 0; i < 8; i++) s += wred[i];
        atomicAdd(&g_accum[b], s * (1.0f / (float)(EN * EN)));
        __threadfence();
        const int old = atomicAdd(&g_cnt[b], 1);
        if (old == GX - 1) {
            const float tot = atomicAdd(&g_accum[b], 0.0f);  // atomic read
            out[b] = tot;
            __threadfence();
            g_accum[b] = 0.0f;   // reset for next graph replay
            g_cnt[b]   = 0;
        }
    }
}

extern "C" void kernel_launch(void* const* d_in, const int* in_sizes, int n_in,
                              void* d_out, int out_size)
{
    const float* x1 = (const float*)d_in[0];
    const float* x2 = (const float*)d_in[1];
    float* out = (float*)d_out;

    dim3 grid(GX, EB);   // (16, 16): 8 dims per CTA, 1 warp per dim
    ed_kernel<<<grid, 256>>>(x1, x2, out);
}

// round 12
// speedup vs baseline: 1.1813x; 1.0440x over previous
#include <cuda_runtime.h>
#include <cstdint>

// Energy distance, B=16, N=M=256, D=128, fp32. Single launch, SINGLE WAVE:
// 128 CTAs (<=148 SMs), 512 threads, 16 warps; each warp owns one (batch,dim)
// column and sorts its 512 merged labeled values entirely in-warp (16 elems/
// thread, normalized all-ascending bitonic, all cross-thread stages via shfl;
// triangle reversals are compile-time register permutations).
// E*N^2 = sum_k (z_{k+1}-z_k)*d_k^2, d = prefix of +/-1 labels (mantissa LSB).
// Cross-CTA fan-in via device scratch + arrival counter (8 CTAs per batch).

#define EB 16
#define EN 256
#define ED 128
#define GX 8           // grid.x = ED/16 (16 dims per CTA, 1 warp per dim)
#define CSTRIDE 648    // floats per staging column (phys max 635)
#define FULL_MASK 0xFFFFFFFFu

__device__ float g_accum[EB];   // zero-init; reset by last CTA each run
__device__ int   g_cnt[EB];

// In-register ascending compare-exchange.
#define CEP(a,b) { const float lo_=fminf((a),(b)), hi_=fmaxf((a),(b)); (a)=lo_; (b)=hi_; }

#define IR_J1 { CEP(v[0],v[1]) CEP(v[2],v[3]) CEP(v[4],v[5]) CEP(v[6],v[7]) \
                CEP(v[8],v[9]) CEP(v[10],v[11]) CEP(v[12],v[13]) CEP(v[14],v[15]) }
#define IR_J2 { CEP(v[0],v[2]) CEP(v[1],v[3]) CEP(v[4],v[6]) CEP(v[5],v[7]) \
                CEP(v[8],v[10]) CEP(v[9],v[11]) CEP(v[12],v[14]) CEP(v[13],v[15]) }
#define IR_J4 { CEP(v[0],v[4]) CEP(v[1],v[5]) CEP(v[2],v[6]) CEP(v[3],v[7]) \
                CEP(v[8],v[12]) CEP(v[9],v[13]) CEP(v[10],v[14]) CEP(v[11],v[15]) }
#define IR_J8 { CEP(v[0],v[8]) CEP(v[1],v[9]) CEP(v[2],v[10]) CEP(v[3],v[11]) \
                CEP(v[4],v[12]) CEP(v[5],v[13]) CEP(v[6],v[14]) CEP(v[7],v[15]) }
#define IR_TRI4  { CEP(v[0],v[3]) CEP(v[1],v[2]) CEP(v[4],v[7]) CEP(v[5],v[6]) \
                   CEP(v[8],v[11]) CEP(v[9],v[10]) CEP(v[12],v[15]) CEP(v[13],v[14]) }
#define IR_TRI8  { CEP(v[0],v[7]) CEP(v[1],v[6]) CEP(v[2],v[5]) CEP(v[3],v[4]) \
                   CEP(v[8],v[15]) CEP(v[9],v[14]) CEP(v[10],v[13]) CEP(v[11],v[12]) }
#define IR_TRI16 { CEP(v[0],v[15]) CEP(v[1],v[14]) CEP(v[2],v[13]) CEP(v[3],v[12]) \
                   CEP(v[4],v[11]) CEP(v[5],v[10]) CEP(v[6],v[9]) CEP(v[7],v[8]) }
#define IR_TAIL { IR_J8 IR_J4 IR_J2 IR_J1 }

// Cross-lane substage via shfl: partner lane^m, same register index.
#define SHS(m, P) { float u_[16]; \
    _Pragma("unroll") for (int r_=0;r_<16;r_++) \
        u_[r_] = __shfl_xor_sync(FULL_MASK, v[r_], (m)); \
    _Pragma("unroll") for (int r_=0;r_<16;r_++) \
        v[r_] = (P) ? fminf(v[r_],u_[r_]) : fmaxf(v[r_],u_[r_]); }

// Cross-lane triangle via shfl: partner lane^m, register index reversed
// (compile-time permutation -- no data movement).
#define SHT(m, P) { float u_[16]; \
    _Pragma("unroll") for (int r_=0;r_<16;r_++) \
        u_[r_] = __shfl_xor_sync(FULL_MASK, v[15-r_], (m)); \
    _Pragma("unroll") for (int r_=0;r_<16;r_++) \
        v[r_] = (P) ? fminf(v[r_],u_[r_]) : fmaxf(v[r_],u_[r_]); }

__global__ __launch_bounds__(512) void ed_kernel(
    const float* __restrict__ x1,
    const float* __restrict__ x2,
    float* __restrict__ out)
{
    __shared__ __align__(16) float stg[16 * CSTRIDE];   // 41.5 KB
    __shared__ float wred[16];

    const int b  = blockIdx.y;
    const int d0 = blockIdx.x << 4;        // 16 dims per CTA
    const int t  = threadIdx.x;            // 0..511
    const int lane = t & 31;
    const int w    = t >> 5;               // warp == column (dim) 0..15

    // ---- Stage: thread t = (sample s, dim-half h): s = t>>1, h = t&1.
    //      Loads both inputs' sample s, dims d0+8h .. d0+8h+7, labels into
    //      mantissa LSB (x1->1, x2->0). Element i = 16*L + r of column c
    //      lives at float offset 20*L + r (pad 4 per 16 -> LDS.128
    //      conflict-free). x1 at i=s, x2 at i=256+s (offset +320).
    {
        const int s = t >> 1;
        const int h = t & 1;
        const size_t off = ((size_t)(b * EN + s)) * ED + d0 + (h << 3);
        const float4 a0 = *(const float4*)(x1 + off);
        const float4 a1 = *(const float4*)(x1 + off + 4);
        const float4 b0 = *(const float4*)(x2 + off);
        const float4 b1 = *(const float4*)(x2 + off + 4);
        const uint32_t av[8] = {
            __float_as_uint(a0.x)|1u, __float_as_uint(a0.y)|1u,
            __float_as_uint(a0.z)|1u, __float_as_uint(a0.w)|1u,
            __float_as_uint(a1.x)|1u, __float_as_uint(a1.y)|1u,
            __float_as_uint(a1.z)|1u, __float_as_uint(a1.w)|1u };
        const uint32_t bv[8] = {
            __float_as_uint(b0.x)&~1u, __float_as_uint(b0.y)&~1u,
            __float_as_uint(b0.z)&~1u, __float_as_uint(b0.w)&~1u,
            __float_as_uint(b1.x)&~1u, __float_as_uint(b1.y)&~1u,
            __float_as_uint(b1.z)&~1u, __float_as_uint(b1.w)&~1u };
        const int pt = s + ((s >> 4) << 2);          // phys(s)
        float* cbase = stg + (h << 3) * CSTRIDE;
        #pragma unroll
        for (int c = 0; c < 8; c++) {
            cbase[c * CSTRIDE + pt]       = __uint_as_float(av[c]);
            cbase[c * CSTRIDE + pt + 320] = __uint_as_float(bv[c]);
        }
    }
    __syncthreads();

    const float* buf = stg + w * CSTRIDE;
    const int base = 20 * lane;

    float v[16];
    {
        const float4 q0=*(const float4*)(buf+base),   q1=*(const float4*)(buf+base+4);
        const float4 q2=*(const float4*)(buf+base+8), q3=*(const float4*)(buf+base+12);
        v[0]=q0.x; v[1]=q0.y; v[2]=q0.z; v[3]=q0.w;
        v[4]=q1.x; v[5]=q1.y; v[6]=q1.z; v[7]=q1.w;
        v[8]=q2.x; v[9]=q2.y; v[10]=q2.z; v[11]=q2.w;
        v[12]=q3.x; v[13]=q3.y; v[14]=q3.z; v[15]=q3.w;
    }

    // keep-min predicates: (i & K/2)==0 maps to one lane bit per level
    const bool P1  = (lane & 1)  == 0;
    const bool P2  = (lane & 2)  == 0;
    const bool P4  = (lane & 4)  == 0;
    const bool P8  = (lane & 8)  == 0;
    const bool P16 = (lane & 16) == 0;

    // ---- Normalized bitonic sort of 512, all in-warp, all-shfl cross-lane ----
    IR_J1                                        // K=2
    IR_TRI4  IR_J1                               // K=4
    IR_TRI8  IR_J2 IR_J1                         // K=8
    IR_TRI16 IR_J4 IR_J2 IR_J1                   // K=16
    SHT(1,  P1)                                       IR_TAIL  // K=32
    SHT(3,  P2)                            SHS(1, P1) IR_TAIL  // K=64
    SHT(7,  P4)                 SHS(2, P2) SHS(1, P1) IR_TAIL  // K=128
    SHT(15, P8)      SHS(4, P4) SHS(2, P2) SHS(1, P1) IR_TAIL  // K=256
    SHT(31, P16) SHS(8, P8) SHS(4, P4) SHS(2, P2) SHS(1, P1) IR_TAIL  // K=512

    // ---- Label prefix d (exact small ints in fp32) ----
    float c[16];
    c[0] = (__float_as_uint(v[0]) & 1u) ? 1.0f : -1.0f;
    #pragma unroll
    for (int r = 1; r < 16; r++)
        c[r] = c[r-1] + ((__float_as_uint(v[r]) & 1u) ? 1.0f : -1.0f);

    float incl = c[15];
    #pragma unroll
    for (int o = 1; o < 32; o <<= 1) {
        const float f = __shfl_up_sync(FULL_MASK, incl, o);
        if (lane >= o) incl += f;
    }
    const float dbase = incl - c[15];

    // Neighbor for the r=15 gap; lane 31's term has d=0 (labels sum to 0),
    // so its (self) shfl value is harmless.
    const float vn = __shfl_down_sync(FULL_MASK, v[0], 1);

    float acc = 0.0f;
    #pragma unroll
    for (int r = 0; r < 15; r++) {
        const float dr = dbase + c[r];
        acc += (v[r+1] - v[r]) * dr * dr;
    }
    {
        const float dr = dbase + c[15];
        acc += (vn - v[15]) * dr * dr;
    }

    // ---- Warp reduce -> CTA reduce -> device scratch fan-in ----
    #pragma unroll
    for (int o = 16; o; o >>= 1)
        acc += __shfl_xor_sync(FULL_MASK, acc, o);
    if (lane == 0) wred[w] = acc;
    __syncthreads();

    if (t == 0) {
        float s = 0.0f;
        #pragma unroll
        for (int i = 0; i < 16; i++) s += wred[i];
        atomicAdd(&g_accum[b], s * (1.0f / (float)(EN * EN)));
        __threadfence();
        const int old = atomicAdd(&g_cnt[b], 1);
        if (old == GX - 1) {
            const float tot = atomicAdd(&g_accum[b], 0.0f);  // atomic read
            out[b] = tot;
            __threadfence();
            g_accum[b] = 0.0f;   // reset for next graph replay
            g_cnt[b]   = 0;
        }
    }
}

extern "C" void kernel_launch(void* const* d_in, const int* in_sizes, int n_in,
                              void* d_out, int out_size)
{
    const float* x1 = (const float*)d_in[0];
    const float* x2 = (const float*)d_in[1];
    float* out = (float*)d_out;

    dim3 grid(GX, EB);   // (8, 16) = 128 CTAs: one wave on 148 SMs
    ed_kernel<<<grid, 512>>>(x1, x2, out);
}